// round 13
// baseline (speedup 1.0000x reference)
#include <cuda_runtime.h>
#include <cstdint>

// Depthwise 9x9 conv, stride 1, pad 4. X:(32,64,256,256) fp32, one shared kernel.
// R12: R11 (image-pair f32x2 packing, best) + occupancy & staging trims:
//  - __launch_bounds__(128, 9): 9 CTAs/SM (smem 207KB, regs capped 56) ->
//    36 warps for latency cover.
//  - float4 staging: LDG.128 x2 + STS.128 x2 per 4 columns, ~6 iterations.
// Main loop unchanged: runtime tap loop, LDC.64 packed {k,k}, depth-3
// pipeline, C=16 chains, conflict-free 8B-aligned LDS.64 (no parity problem
// because both f32x2 lanes are different IMAGES at the same (i,j)).
// CTA 128 thr = 64 cols x 2 rowgroups x 16 rows -> 64x32 tile x 2 images.

#define IMG 256
#define IMGSZ (IMG * IMG)
#define SROW 144                           // interleaved floats per smem row
#define SROWS 40                           // 32 + 8 halo rows
#define NU4 (SROWS * 18)                   // 720 four-col units
#define SMEM_BYTES (SROWS * SROW * 4)      // 23040

__device__ unsigned long long d_kstage[81];
__constant__ unsigned long long cKpack[81];

__device__ __forceinline__ unsigned long long pack2(float lo, float hi) {
    unsigned long long r;
    asm("mov.b64 %0, {%1, %2};" : "=l"(r) : "f"(lo), "f"(hi));
    return r;
}

__device__ __forceinline__ void ffma2(unsigned long long& d,
                                      unsigned long long a,
                                      unsigned long long b) {
    asm("fma.rn.f32x2 %0, %1, %2, %0;" : "+l"(d) : "l"(a), "l"(b));
}

__global__ void pack_kernel(const float* __restrict__ K) {
    int i = threadIdx.x;
    if (i < 81) {
        float v = K[i];
        d_kstage[i] = pack2(v, v);
    }
}

__global__ __launch_bounds__(128, 9)
void conv9x9_kernel(const float* __restrict__ X,
                    float* __restrict__ out) {
    extern __shared__ float smem[];

    const int bx    = blockIdx.x;
    const int pair  = bx >> 5;             // 1024 image pairs
    const int t32   = bx & 31;             // 4 colstrips x 8 rowstrips
    const int row0  = (t32 >> 2) * 32;
    const int col0  = (t32 & 3) * 64;

    const float* __restrict__ XA = X + (size_t)(2 * pair)     * IMGSZ;
    const float* __restrict__ XB = X + (size_t)(2 * pair + 1) * IMGSZ;
    const int tid = threadIdx.x;

    // ---- Stage interleaved tile, float4 per image per unit (4 orig cols) ----
    {
        int r  = tid / 18;
        int c4 = tid - r * 18;
        int idx = tid;
        #pragma unroll 1
        while (idx < NU4) {
            const int gr  = row0 - 4 + r;
            const int gc0 = col0 - 4 + 4 * c4;   // 16B-aligned; fully in or out
            float4 a = make_float4(0.f, 0.f, 0.f, 0.f);
            float4 b = make_float4(0.f, 0.f, 0.f, 0.f);
            if ((unsigned)gr < IMG && (unsigned)gc0 < IMG) {
                a = *(const float4*)&XA[gr * IMG + gc0];
                b = *(const float4*)&XB[gr * IMG + gc0];
            }
            // interleaved: orig col c -> smem floats (2c, 2c+1) = (A, B)
            float* dst = &smem[r * SROW + 8 * c4];
            *(float4*)(dst)     = make_float4(a.x, b.x, a.y, b.y);
            *(float4*)(dst + 4) = make_float4(a.z, b.z, a.w, b.w);

            idx += 128;                    // 128 = 7*18 + 2
            r  += 7;
            c4 += 2;
            if (c4 >= 18) { c4 -= 18; r += 1; }
        }
    }
    __syncthreads();

    const int j     = tid & 63;            // column within tile (one per thread)
    const int rg    = tid >> 6;            // 2 rowgroups x 16 rows
    const int rbase = rg * 16;

    unsigned long long acc[16];
    #pragma unroll
    for (int i = 0; i < 16; ++i) acc[i] = 0ull;

    // Runtime loop over the 9 horizontal taps; small body, L0-resident.
    #pragma unroll 1
    for (int g = 0; g < 9; ++g) {
        // Pre-packed {k,k} coefficients for this tap: 9 bare LDC.64.
        unsigned long long kr[9];
        #pragma unroll
        for (int u = 0; u < 9; ++u)
            kr[u] = cKpack[u * 9 + g];

        // Window base: interleaved col (j+g) -> float offset 2*(j+g). 8B-aligned.
        const float* base = &smem[rbase * SROW + 2 * (j + g)];

        // Depth-3 rotating pipeline: load t+2 before computing t.
        unsigned long long P[3];
        P[0] = *(const unsigned long long*)(base);
        P[1] = *(const unsigned long long*)(base + SROW);
        #pragma unroll
        for (int t = 0; t < 24; ++t) {
            if (t + 2 < 24)
                P[(t + 2) % 3] =
                    *(const unsigned long long*)(base + (t + 2) * SROW);
            const unsigned long long Pc = P[t % 3];
            #pragma unroll
            for (int u = 0; u < 9; ++u) {
                const int o = t - u;       // output row in chain
                if (o >= 0 && o < 16)
                    ffma2(acc[o], Pc, kr[u]);
            }
        }
    }

    float* __restrict__ OA = out + (size_t)(2 * pair)     * IMGSZ;
    float* __restrict__ OB = out + (size_t)(2 * pair + 1) * IMGSZ;
    #pragma unroll
    for (int o = 0; o < 16; ++o) {
        float lo, hi;
        asm("mov.b64 {%0, %1}, %2;" : "=f"(lo), "=f"(hi) : "l"(acc[o]));
        const int off = (row0 + rbase + o) * IMG + col0 + j;
        OA[off] = lo;
        OB[off] = hi;
    }
}

extern "C" void kernel_launch(void* const* d_in, const int* in_sizes, int n_in,
                              void* d_out, int out_size) {
    const float* X = (const float*)d_in[0];
    const float* K = (const float*)d_in[1];
    if (n_in >= 2 && in_sizes[0] == 81) {  // metadata-order safety
        const float* t = X; X = K; K = t;
    }
    pack_kernel<<<1, 128>>>(K);
    void* stage_ptr = nullptr;
    cudaGetSymbolAddress(&stage_ptr, d_kstage);
    cudaMemcpyToSymbolAsync(cKpack, stage_ptr, 81 * sizeof(unsigned long long),
                            0, cudaMemcpyDeviceToDevice, 0);
    cudaFuncSetAttribute(conv9x9_kernel,
                         cudaFuncAttributeMaxDynamicSharedMemorySize,
                         SMEM_BYTES);
    conv9x9_kernel<<<32768, 128, SMEM_BYTES>>>(X, (float*)d_out);
}

// round 14
// speedup vs baseline: 1.1025x; 1.1025x over previous
#include <cuda_runtime.h>
#include <cstdint>

// Depthwise 9x9 conv, stride 1, pad 4. X:(32,64,256,256) fp32, one shared kernel.
// R13: TWO-COLUMN chains sharing windows. Cols (jA, jA+1) need windows
// jA..jA+9: 10 loads/row serve both columns (LDS/output 6.75 -> 3.75), raising
// FFMA2's issue share (the fma pipe holds 2cyc/FFMA2, so pipe% = 2x share).
//  - window w feeds col A at tap v=w and col B at tap v=w-1; coefficient sets
//    rotate through kra/krb via a 2-unrolled w-loop (no copy MOVs).
//  - w=0 (A tap0) and w=9 (B tap8) are separate sections: zero wasted FMAs.
//  - image-pair f32x2 packing (R11): both lanes same (i,j), no parity problem.
//  - thread = 2 cols x 16 rows x 2 images (accA/accB = 64 regs); CTA 128 thr
//    = 32 colunits x 4 rowgroups -> 64x64 tile x 2 images; smem 41.5KB,
//    __launch_bounds__(128,4).

#define IMG 256
#define IMGSZ (IMG * IMG)
#define SROW 144                           // interleaved floats per smem row
#define SROWS 72                           // 64 + 8 halo rows
#define NU4 (SROWS * 18)                   // 1296 four-col staging units
#define SMEM_BYTES (SROWS * SROW * 4)      // 41472

__device__ unsigned long long d_kstage[81];
__constant__ unsigned long long cKpack[81];

__device__ __forceinline__ unsigned long long pack2(float lo, float hi) {
    unsigned long long r;
    asm("mov.b64 %0, {%1, %2};" : "=l"(r) : "f"(lo), "f"(hi));
    return r;
}

__device__ __forceinline__ void ffma2(unsigned long long& d,
                                      unsigned long long a,
                                      unsigned long long b) {
    asm("fma.rn.f32x2 %0, %1, %2, %0;" : "+l"(d) : "l"(a), "l"(b));
}

__global__ void pack_kernel(const float* __restrict__ K) {
    int i = threadIdx.x;
    if (i < 81) {
        float v = K[i];
        d_kstage[i] = pack2(v, v);
    }
}

// One window pass: 24 rows, FFMA2 into accA (coeff ka) and/or accB (kb).
template <bool DO_A, bool DO_B>
__device__ __forceinline__ void window_pass(
    const float* base, unsigned long long* accA, unsigned long long* accB,
    const unsigned long long* ka, const unsigned long long* kb)
{
    unsigned long long P[3];
    P[0] = *(const unsigned long long*)(base);
    P[1] = *(const unsigned long long*)(base + SROW);
    #pragma unroll
    for (int t = 0; t < 24; ++t) {
        if (t + 2 < 24)
            P[(t + 2) % 3] =
                *(const unsigned long long*)(base + (t + 2) * SROW);
        const unsigned long long Pc = P[t % 3];
        #pragma unroll
        for (int u = 0; u < 9; ++u) {
            const int o = t - u;
            if (o >= 0 && o < 16) {
                if (DO_A) ffma2(accA[o], Pc, ka[u]);
                if (DO_B) ffma2(accB[o], Pc, kb[u]);
            }
        }
    }
}

__global__ __launch_bounds__(128, 4)
void conv9x9_kernel(const float* __restrict__ X,
                    float* __restrict__ out) {
    extern __shared__ float smem[];

    const int bx    = blockIdx.x;
    const int pair  = bx >> 4;             // 1024 image pairs
    const int t16   = bx & 15;             // 4x4 tiles of 64x64
    const int row0  = (t16 >> 2) * 64;
    const int col0  = (t16 & 3) * 64;

    const float* __restrict__ XA = X + (size_t)(2 * pair)     * IMGSZ;
    const float* __restrict__ XB = X + (size_t)(2 * pair + 1) * IMGSZ;
    const int tid = threadIdx.x;

    // ---- Stage interleaved tile: float4 per image per 4-col unit ----
    {
        int r  = tid / 18;
        int c4 = tid - r * 18;
        int idx = tid;
        #pragma unroll 1
        while (idx < NU4) {
            const int gr  = row0 - 4 + r;
            const int gc0 = col0 - 4 + 4 * c4;   // 16B-aligned; fully in or out
            float4 a = make_float4(0.f, 0.f, 0.f, 0.f);
            float4 b = make_float4(0.f, 0.f, 0.f, 0.f);
            if ((unsigned)gr < IMG && (unsigned)gc0 < IMG) {
                a = *(const float4*)&XA[gr * IMG + gc0];
                b = *(const float4*)&XB[gr * IMG + gc0];
            }
            float* dst = &smem[r * SROW + 8 * c4];
            *(float4*)(dst)     = make_float4(a.x, b.x, a.y, b.y);
            *(float4*)(dst + 4) = make_float4(a.z, b.z, a.w, b.w);

            idx += 128;                    // 128 = 7*18 + 2
            r  += 7;
            c4 += 2;
            if (c4 >= 18) { c4 -= 18; r += 1; }
        }
    }
    __syncthreads();

    const int cu    = tid & 31;            // colunit: output cols jA, jA+1
    const int rg    = tid >> 5;            // 4 rowgroups x 16 rows
    const int jA    = 2 * cu;
    const int rbase = rg * 16;
    const float* wbase0 = &smem[rbase * SROW + 2 * jA];  // window w: +2w floats

    unsigned long long accA[16], accB[16];
    #pragma unroll
    for (int i = 0; i < 16; ++i) { accA[i] = 0ull; accB[i] = 0ull; }

    unsigned long long kra[9], krb[9];

    // Section 1: window 0 -> col A, tap v=0.
    #pragma unroll
    for (int u = 0; u < 9; ++u) kra[u] = cKpack[u * 9 + 0];
    window_pass<true, false>(wbase0, accA, accB, kra, krb);

    // Section 2: windows w=1..8, unrolled by 2 to rotate coefficient buffers.
    // Window w: col A tap v=w, col B tap v=w-1.
    #pragma unroll 1
    for (int w = 1; w <= 8; w += 2) {
        // odd step: krb <- v=w ; A uses krb, B uses kra (v=w-1)
        #pragma unroll
        for (int u = 0; u < 9; ++u) krb[u] = cKpack[u * 9 + w];
        window_pass<true, true>(wbase0 + 2 * w, accA, accB, krb, kra);
        // even step: kra <- v=w+1 ; A uses kra, B uses krb (v=w)
        #pragma unroll
        for (int u = 0; u < 9; ++u) kra[u] = cKpack[u * 9 + w + 1];
        window_pass<true, true>(wbase0 + 2 * (w + 1), accA, accB, kra, krb);
    }

    // Section 3: window 9 -> col B, tap v=8 (held in kra after the loop).
    window_pass<false, true>(wbase0 + 2 * 9, accA, accB, krb, kra);

    float* __restrict__ OA = out + (size_t)(2 * pair)     * IMGSZ;
    float* __restrict__ OB = out + (size_t)(2 * pair + 1) * IMGSZ;
    #pragma unroll
    for (int o = 0; o < 16; ++o) {
        float aA, bA, aB, bB;   // a/b = image, A/B = column
        asm("mov.b64 {%0, %1}, %2;" : "=f"(aA), "=f"(bA) : "l"(accA[o]));
        asm("mov.b64 {%0, %1}, %2;" : "=f"(aB), "=f"(bB) : "l"(accB[o]));
        const int off = (row0 + rbase + o) * IMG + col0 + jA;
        *(float2*)&OA[off] = make_float2(aA, aB);
        *(float2*)&OB[off] = make_float2(bA, bB);
    }
}

extern "C" void kernel_launch(void* const* d_in, const int* in_sizes, int n_in,
                              void* d_out, int out_size) {
    const float* X = (const float*)d_in[0];
    const float* K = (const float*)d_in[1];
    if (n_in >= 2 && in_sizes[0] == 81) {  // metadata-order safety
        const float* t = X; X = K; K = t;
    }
    pack_kernel<<<1, 128>>>(K);
    void* stage_ptr = nullptr;
    cudaGetSymbolAddress(&stage_ptr, d_kstage);
    cudaMemcpyToSymbolAsync(cKpack, stage_ptr, 81 * sizeof(unsigned long long),
                            0, cudaMemcpyDeviceToDevice, 0);
    cudaFuncSetAttribute(conv9x9_kernel,
                         cudaFuncAttributeMaxDynamicSharedMemorySize,
                         SMEM_BYTES);
    conv9x9_kernel<<<16384, 128, SMEM_BYTES>>>(X, (float*)d_out);
}